// round 12
// baseline (speedup 1.0000x reference)
#include <cuda_runtime.h>
#include <cuda_fp16.h>
#include <cstdint>

#define N_NODES 50000
#define N_EDGES 600000
#define F_MID 128
#define F_OUT 64
#define BUCKET 64                         // max in-degree slots per node
#define GEMM1_BLOCKS ((N_NODES + 127) / 128)          // 391
#define FILL_BLOCKS  ((N_EDGES + 255) / 256)          // 2344

// ---------------- scratch (static __device__, 256B-aligned) ----------------
__device__ __align__(256) __half g_h1h[N_NODES * F_MID]; // x @ W1   (fp16)
__device__ __align__(256) float  g_a1[N_NODES * F_MID];  // relu(agg1 + b1)
__device__ __align__(256) __half g_h2h[N_NODES * F_OUT]; // a1 @ W2  (fp16)
__device__ __align__(256) float  g_dinv[N_NODES];
__device__ __align__(256) int    g_deg[N_NODES];         // atomic cursor == in-degree
__device__ __align__(256) int    g_esrc[N_NODES * BUCKET];
__device__ int g_is64;   // 1 if edge_index is int64, 0 if int32

__device__ __forceinline__ int load_edge(const void* ei, long long idx) {
    if (g_is64) return (int)((const long long*)ei)[idx];
    return ((const int*)ei)[idx];
}

// ---------------- zero degrees + dtype sniff --------------------------------
// int64 vals < 50000 look like [v,0,v,0,...] as int32 pairs
__global__ void zero_detect_kernel(const void* __restrict__ ei) {
    int i = blockIdx.x * blockDim.x + threadIdx.x;
    if (i < N_NODES) g_deg[i] = 0;
    if (i == 0) {
        const int* p = (const int*)ei;
        int allz = 1;
        for (int k = 0; k < 128; k++)
            if (p[2 * k + 1] != 0) { allz = 0; break; }
        g_is64 = allz;
    }
}

// ---------------- dinv from final degrees -----------------------------------
__global__ void prep_dinv_kernel() {
    int i = blockIdx.x * blockDim.x + threadIdx.x;
    if (i < N_NODES)
        g_dinv[i] = rsqrtf((float)(g_deg[i] + 1));  // +1 self-loop; always > 0
}

// ---------------- tf32 tensor-core GEMM tile (device fn) --------------------
// Chalf[128 rows][BN] = A[128 rows,128] * B[128,BN]; 256 thr = 8 warps (2x4).
__device__ __forceinline__ uint32_t f2tf32(float f) {
    uint32_t u;
    asm("cvt.rna.tf32.f32 %0, %1;" : "=r"(u) : "f"(f));
    return u;
}

template <int BN>
__device__ __forceinline__ void gemm_tile(const float* __restrict__ A,
                                          const float* __restrict__ B,
                                          __half* __restrict__ C, int block) {
    constexpr int BM = 128, BK = 32;
    constexpr int MT = 4;
    constexpr int NT = (BN / 4) / 8;      // 4 (BN=128) or 2 (BN=64)
    constexpr int NAv = 4;
    constexpr int NBv = BN / 32;
    const int M = N_NODES;

    __shared__ float As[BM][BK + 4];
    __shared__ float Bs[BK][BN + 4];

    int tid = threadIdx.x;
    int lane = tid & 31;
    int w = tid >> 5;
    int warp_m = w >> 2, warp_n = w & 3;
    int mrow0 = warp_m * 64;
    int ncol0 = warp_n * (BN / 4);
    int g = lane >> 2, q = lane & 3;
    int row0 = block * BM;

    float acc[MT][NT][4];
    #pragma unroll
    for (int i = 0; i < MT; i++)
        #pragma unroll
        for (int j = 0; j < NT; j++)
            #pragma unroll
            for (int k = 0; k < 4; k++) acc[i][j][k] = 0.f;

    float4 ra[NAv], rb[NBv];
    auto fetch = [&](int kb) {
        #pragma unroll
        for (int k = 0; k < NAv; k++) {
            int idx = tid + k * 256;
            int ar = idx >> 3, ac4 = idx & 7;
            int gr = row0 + ar;
            ra[k] = (gr < M) ? *(const float4*)&A[gr * 128 + kb + ac4 * 4]
                             : make_float4(0.f, 0.f, 0.f, 0.f);
        }
        #pragma unroll
        for (int k = 0; k < NBv; k++) {
            int idx = tid + k * 256;
            int br = idx / (BN / 4), bc4 = idx % (BN / 4);
            rb[k] = *(const float4*)&B[(kb + br) * BN + bc4 * 4];
        }
    };
    auto commit = [&]() {
        #pragma unroll
        for (int k = 0; k < NAv; k++) {
            int idx = tid + k * 256;
            int ar = idx >> 3, ac4 = idx & 7;
            *(float4*)&As[ar][ac4 * 4] = ra[k];
        }
        #pragma unroll
        for (int k = 0; k < NBv; k++) {
            int idx = tid + k * 256;
            int br = idx / (BN / 4), bc4 = idx % (BN / 4);
            *(float4*)&Bs[br][bc4 * 4] = rb[k];
        }
    };

    fetch(0);
    #pragma unroll
    for (int t = 0; t < 128 / BK; t++) {
        commit();
        __syncthreads();
        if (t < 128 / BK - 1) fetch((t + 1) * BK);
        #pragma unroll
        for (int ks = 0; ks < BK / 8; ks++) {
            int k0 = ks * 8;
            uint32_t af[MT][4];
            #pragma unroll
            for (int mt = 0; mt < MT; mt++) {
                int r = mrow0 + mt * 16 + g;
                af[mt][0] = f2tf32(As[r][k0 + q]);
                af[mt][1] = f2tf32(As[r + 8][k0 + q]);
                af[mt][2] = f2tf32(As[r][k0 + q + 4]);
                af[mt][3] = f2tf32(As[r + 8][k0 + q + 4]);
            }
            uint32_t bf[NT][2];
            #pragma unroll
            for (int nt = 0; nt < NT; nt++) {
                int c = ncol0 + nt * 8 + g;
                bf[nt][0] = f2tf32(Bs[k0 + q][c]);
                bf[nt][1] = f2tf32(Bs[k0 + q + 4][c]);
            }
            #pragma unroll
            for (int mt = 0; mt < MT; mt++)
                #pragma unroll
                for (int nt = 0; nt < NT; nt++) {
                    asm volatile(
                        "mma.sync.aligned.m16n8k8.row.col.f32.tf32.tf32.f32 "
                        "{%0,%1,%2,%3}, {%4,%5,%6,%7}, {%8,%9}, {%0,%1,%2,%3};"
                        : "+f"(acc[mt][nt][0]), "+f"(acc[mt][nt][1]),
                          "+f"(acc[mt][nt][2]), "+f"(acc[mt][nt][3])
                        : "r"(af[mt][0]), "r"(af[mt][1]),
                          "r"(af[mt][2]), "r"(af[mt][3]),
                          "r"(bf[nt][0]), "r"(bf[nt][1]));
                }
        }
        __syncthreads();
    }

    #pragma unroll
    for (int mt = 0; mt < MT; mt++) {
        int r = mrow0 + mt * 16 + g;
        int gr0 = row0 + r, gr1 = gr0 + 8;
        #pragma unroll
        for (int nt = 0; nt < NT; nt++) {
            int c = ncol0 + nt * 8 + 2 * q;
            if (gr0 < M)
                *(__half2*)&C[gr0 * BN + c] =
                    __floats2half2_rn(acc[mt][nt][0], acc[mt][nt][1]);
            if (gr1 < M)
                *(__half2*)&C[gr1 * BN + c] =
                    __floats2half2_rn(acc[mt][nt][2], acc[mt][nt][3]);
        }
    }
}

// ---------------- fused: GEMM1 tiles + bucket fill --------------------------
// blocks [0, GEMM1_BLOCKS): h1 = x@W1 (tensor pipe)
// blocks [GEMM1_BLOCKS, +FILL_BLOCKS): bucket-append edges (LSU/atomics)
__global__ void gemm1_fill_kernel(const float* __restrict__ x,
                                  const float* __restrict__ W1,
                                  const void* __restrict__ ei) {
    if (blockIdx.x < GEMM1_BLOCKS) {
        gemm_tile<128>(x, W1, g_h1h, blockIdx.x);
    } else {
        int e = (blockIdx.x - GEMM1_BLOCKS) * blockDim.x + threadIdx.x;
        if (e < N_EDGES) {
            int s = load_edge(ei, e);
            int d = load_edge(ei, (long long)N_EDGES + e);
            if ((unsigned)d < (unsigned)N_NODES && (unsigned)s < (unsigned)N_NODES) {
                int idx = atomicAdd(&g_deg[d], 1);
                if (idx < BUCKET) g_esrc[d * BUCKET + idx] = s;
            }
        }
    }
}

__global__ void gemm2_kernel(const float* __restrict__ W2) {
    gemm_tile<64>((const float*)g_a1, W2, g_h2h, blockIdx.x);
}

// ---------------- aggregation: warp-per-node gather (fp16 source) ----------
__device__ __forceinline__ float4 h4_to_f4(uint2 r) {
    __half2 a = *reinterpret_cast<__half2*>(&r.x);
    __half2 b = *reinterpret_cast<__half2*>(&r.y);
    float2 fa = __half22float2(a), fb = __half22float2(b);
    return make_float4(fa.x, fa.y, fb.x, fb.y);
}

// g_a1[i] = relu( dinv[i]^2*h1[i] + sum_e dinv[src]*dinv[i]*h1[src] + b1 )
__global__ void agg_relu_bias_128_kernel(const float* __restrict__ bias) {
    int gw = (blockIdx.x * blockDim.x + threadIdx.x) >> 5;
    int lane = threadIdx.x & 31;
    if (gw >= N_NODES) return;
    int node = gw;
    float di = g_dinv[node];
    const uint2* hv = (const uint2*)g_h1h;   // 4 halves per uint2; 32/row
    float4 a = h4_to_f4(hv[node * 32 + lane]);
    float w0 = di * di;
    float4 acc = make_float4(w0 * a.x, w0 * a.y, w0 * a.z, w0 * a.w);
    int n = g_deg[node];
    if (n > BUCKET) n = BUCKET;
    const int* row = &g_esrc[node * BUCKET];
    for (int j = 0; j < n; j++) {
        int s = row[j];
        float w = di * g_dinv[s];
        float4 v = h4_to_f4(hv[s * 32 + lane]);
        acc.x = fmaf(w, v.x, acc.x);
        acc.y = fmaf(w, v.y, acc.y);
        acc.z = fmaf(w, v.z, acc.z);
        acc.w = fmaf(w, v.w, acc.w);
    }
    float bx = bias[lane * 4 + 0], by = bias[lane * 4 + 1];
    float bz = bias[lane * 4 + 2], bw = bias[lane * 4 + 3];
    acc.x = fmaxf(acc.x + bx, 0.f);
    acc.y = fmaxf(acc.y + by, 0.f);
    acc.z = fmaxf(acc.z + bz, 0.f);
    acc.w = fmaxf(acc.w + bw, 0.f);
    ((float4*)g_a1)[node * 32 + lane] = acc;
}

// F=64: 2 halves per lane, + bias, NO relu (final layer), writes fp32 d_out
__global__ void agg_bias_64_kernel(const float* __restrict__ bias,
                                   float* __restrict__ out) {
    int gw = (blockIdx.x * blockDim.x + threadIdx.x) >> 5;
    int lane = threadIdx.x & 31;
    if (gw >= N_NODES) return;
    int node = gw;
    float di = g_dinv[node];
    const uint32_t* hv = (const uint32_t*)g_h2h;  // 2 halves per u32; 32/row
    float2 a = __half22float2(*reinterpret_cast<const __half2*>(&hv[node * 32 + lane]));
    float w0 = di * di;
    float2 acc = make_float2(w0 * a.x, w0 * a.y);
    int n = g_deg[node];
    if (n > BUCKET) n = BUCKET;
    const int* row = &g_esrc[node * BUCKET];
    for (int j = 0; j < n; j++) {
        int s = row[j];
        float w = di * g_dinv[s];
        uint32_t raw = hv[s * 32 + lane];
        float2 v = __half22float2(*reinterpret_cast<__half2*>(&raw));
        acc.x = fmaf(w, v.x, acc.x);
        acc.y = fmaf(w, v.y, acc.y);
    }
    acc.x += bias[lane * 2 + 0];
    acc.y += bias[lane * 2 + 1];
    out[node * 64 + lane * 2 + 0] = acc.x;
    out[node * 64 + lane * 2 + 1] = acc.y;
}

// ---------------- launch ----------------------------------------------------
extern "C" void kernel_launch(void* const* d_in, const int* in_sizes, int n_in,
                              void* d_out, int out_size) {
    const float* x  = (const float*)d_in[0];
    const void*  ei = d_in[1];                 // int32 or int64 — sniffed on device
    const float* W1 = (const float*)d_in[2];
    const float* b1 = (const float*)d_in[3];
    const float* W2 = (const float*)d_in[4];
    const float* b2 = (const float*)d_in[5];
    float* out = (float*)d_out;

    // 1. zero degree cursors + dtype sniff
    zero_detect_kernel<<<(N_NODES + 255) / 256, 256>>>(ei);
    // 2. fused: h1 = x@W1 (tensor) || bucket-append edges (atomics)
    gemm1_fill_kernel<<<GEMM1_BLOCKS + FILL_BLOCKS, 256>>>(x, W1, ei);
    // 3. dinv from final degrees
    prep_dinv_kernel<<<(N_NODES + 255) / 256, 256>>>();
    // 4. a1 = relu(agg(h1) + b1)
    agg_relu_bias_128_kernel<<<(N_NODES * 32 + 255) / 256, 256>>>(b1);
    // 5. h2 = a1@W2
    gemm2_kernel<<<GEMM1_BLOCKS, 256>>>(W2);
    // 6. out = agg(h2) + b2
    agg_bias_64_kernel<<<(N_NODES * 32 + 255) / 256, 256>>>(b2, out);
}

// round 14
// speedup vs baseline: 1.0932x; 1.0932x over previous
#include <cuda_runtime.h>
#include <cuda_fp16.h>
#include <cstdint>

#define N_NODES 50000
#define N_EDGES 600000
#define F_MID 128
#define F_OUT 64
#define BUCKET 64                         // max in-degree slots per node
#define GEMM_BLOCKS ((N_NODES + 127) / 128)           // 391

// ---------------- scratch (static __device__, 256B-aligned) ----------------
__device__ __align__(256) __half g_h1h[N_NODES * F_MID]; // x @ W1   (fp16)
__device__ __align__(256) float  g_a1[N_NODES * F_MID];  // relu(agg1 + b1)
__device__ __align__(256) __half g_h2h[N_NODES * F_OUT]; // a1 @ W2  (fp16)
__device__ __align__(256) int    g_deg[N_NODES];         // atomic cursor == in-degree
__device__ __align__(256) int    g_esrc[N_NODES * BUCKET];
__device__ int g_is64;   // 1 if edge_index is int64, 0 if int32

__device__ __forceinline__ int load_edge(const void* ei, long long idx) {
    if (g_is64) return (int)((const long long*)ei)[idx];
    return ((const int*)ei)[idx];
}

// ---------------- zero degrees + dtype sniff --------------------------------
// int64 vals < 50000 look like [v,0,v,0,...] as int32 pairs
__global__ void zero_detect_kernel(const void* __restrict__ ei) {
    int i = blockIdx.x * blockDim.x + threadIdx.x;
    if (i < N_NODES) g_deg[i] = 0;
    if (i == 0) {
        const int* p = (const int*)ei;
        int allz = 1;
        for (int k = 0; k < 128; k++)
            if (p[2 * k + 1] != 0) { allz = 0; break; }
        g_is64 = allz;
    }
}

// ---------------- bucket fill (standalone, full occupancy) ------------------
__global__ void fill_kernel(const void* __restrict__ ei) {
    int e = blockIdx.x * blockDim.x + threadIdx.x;
    if (e < N_EDGES) {
        int s = load_edge(ei, e);
        int d = load_edge(ei, (long long)N_EDGES + e);
        if ((unsigned)d < (unsigned)N_NODES && (unsigned)s < (unsigned)N_NODES) {
            int idx = atomicAdd(&g_deg[d], 1);
            if (idx < BUCKET) g_esrc[d * BUCKET + idx] = s;
        }
    }
}

// ---------------- tf32 tensor-core GEMM tile (device fn) --------------------
// Chalf[128 rows][BN] = A[128 rows,128] * B[128,BN]; 256 thr = 8 warps (2x4).
__device__ __forceinline__ uint32_t f2tf32(float f) {
    uint32_t u;
    asm("cvt.rna.tf32.f32 %0, %1;" : "=r"(u) : "f"(f));
    return u;
}

template <int BN>
__device__ __forceinline__ void gemm_tile(const float* __restrict__ A,
                                          const float* __restrict__ B,
                                          __half* __restrict__ C, int block) {
    constexpr int BM = 128, BK = 32;
    constexpr int MT = 4;
    constexpr int NT = (BN / 4) / 8;      // 4 (BN=128) or 2 (BN=64)
    constexpr int NAv = 4;
    constexpr int NBv = BN / 32;
    const int M = N_NODES;

    __shared__ float As[BM][BK + 4];
    __shared__ float Bs[BK][BN + 4];

    int tid = threadIdx.x;
    int lane = tid & 31;
    int w = tid >> 5;
    int warp_m = w >> 2, warp_n = w & 3;
    int mrow0 = warp_m * 64;
    int ncol0 = warp_n * (BN / 4);
    int g = lane >> 2, q = lane & 3;
    int row0 = block * BM;

    float acc[MT][NT][4];
    #pragma unroll
    for (int i = 0; i < MT; i++)
        #pragma unroll
        for (int j = 0; j < NT; j++)
            #pragma unroll
            for (int k = 0; k < 4; k++) acc[i][j][k] = 0.f;

    float4 ra[NAv], rb[NBv];
    auto fetch = [&](int kb) {
        #pragma unroll
        for (int k = 0; k < NAv; k++) {
            int idx = tid + k * 256;
            int ar = idx >> 3, ac4 = idx & 7;
            int gr = row0 + ar;
            ra[k] = (gr < M) ? *(const float4*)&A[gr * 128 + kb + ac4 * 4]
                             : make_float4(0.f, 0.f, 0.f, 0.f);
        }
        #pragma unroll
        for (int k = 0; k < NBv; k++) {
            int idx = tid + k * 256;
            int br = idx / (BN / 4), bc4 = idx % (BN / 4);
            rb[k] = *(const float4*)&B[(kb + br) * BN + bc4 * 4];
        }
    };
    auto commit = [&]() {
        #pragma unroll
        for (int k = 0; k < NAv; k++) {
            int idx = tid + k * 256;
            int ar = idx >> 3, ac4 = idx & 7;
            *(float4*)&As[ar][ac4 * 4] = ra[k];
        }
        #pragma unroll
        for (int k = 0; k < NBv; k++) {
            int idx = tid + k * 256;
            int br = idx / (BN / 4), bc4 = idx % (BN / 4);
            *(float4*)&Bs[br][bc4 * 4] = rb[k];
        }
    };

    fetch(0);
    #pragma unroll
    for (int t = 0; t < 128 / BK; t++) {
        commit();
        __syncthreads();
        if (t < 128 / BK - 1) fetch((t + 1) * BK);
        #pragma unroll
        for (int ks = 0; ks < BK / 8; ks++) {
            int k0 = ks * 8;
            uint32_t af[MT][4];
            #pragma unroll
            for (int mt = 0; mt < MT; mt++) {
                int r = mrow0 + mt * 16 + g;
                af[mt][0] = f2tf32(As[r][k0 + q]);
                af[mt][1] = f2tf32(As[r + 8][k0 + q]);
                af[mt][2] = f2tf32(As[r][k0 + q + 4]);
                af[mt][3] = f2tf32(As[r + 8][k0 + q + 4]);
            }
            uint32_t bf[NT][2];
            #pragma unroll
            for (int nt = 0; nt < NT; nt++) {
                int c = ncol0 + nt * 8 + g;
                bf[nt][0] = f2tf32(Bs[k0 + q][c]);
                bf[nt][1] = f2tf32(Bs[k0 + q + 4][c]);
            }
            #pragma unroll
            for (int mt = 0; mt < MT; mt++)
                #pragma unroll
                for (int nt = 0; nt < NT; nt++) {
                    asm volatile(
                        "mma.sync.aligned.m16n8k8.row.col.f32.tf32.tf32.f32 "
                        "{%0,%1,%2,%3}, {%4,%5,%6,%7}, {%8,%9}, {%0,%1,%2,%3};"
                        : "+f"(acc[mt][nt][0]), "+f"(acc[mt][nt][1]),
                          "+f"(acc[mt][nt][2]), "+f"(acc[mt][nt][3])
                        : "r"(af[mt][0]), "r"(af[mt][1]),
                          "r"(af[mt][2]), "r"(af[mt][3]),
                          "r"(bf[nt][0]), "r"(bf[nt][1]));
                }
        }
        __syncthreads();
    }

    #pragma unroll
    for (int mt = 0; mt < MT; mt++) {
        int r = mrow0 + mt * 16 + g;
        int gr0 = row0 + r, gr1 = gr0 + 8;
        #pragma unroll
        for (int nt = 0; nt < NT; nt++) {
            int c = ncol0 + nt * 8 + 2 * q;
            if (gr0 < M)
                *(__half2*)&C[gr0 * BN + c] =
                    __floats2half2_rn(acc[mt][nt][0], acc[mt][nt][1]);
            if (gr1 < M)
                *(__half2*)&C[gr1 * BN + c] =
                    __floats2half2_rn(acc[mt][nt][2], acc[mt][nt][3]);
        }
    }
}

__global__ void gemm1_kernel(const float* __restrict__ x,
                             const float* __restrict__ W1) {
    gemm_tile<128>(x, W1, g_h1h, blockIdx.x);
}

__global__ void gemm2_kernel(const float* __restrict__ W2) {
    gemm_tile<64>((const float*)g_a1, W2, g_h2h, blockIdx.x);
}

// ---------------- aggregation: warp-per-node, lane-preloaded edges ---------
__device__ __forceinline__ float4 h4_to_f4(uint2 r) {
    __half2 a = *reinterpret_cast<__half2*>(&r.x);
    __half2 b = *reinterpret_cast<__half2*>(&r.y);
    float2 fa = __half22float2(a), fb = __half22float2(b);
    return make_float4(fa.x, fa.y, fb.x, fb.y);
}

// g_a1[i] = relu( dinv_i^2*h1[i] + sum_e dinv_s*dinv_i*h1[s] + b1 ), F=128
__global__ void agg_relu_bias_128_kernel(const float* __restrict__ bias) {
    int gw = (blockIdx.x * blockDim.x + threadIdx.x) >> 5;
    int lane = threadIdx.x & 31;
    if (gw >= N_NODES) return;
    int node = gw;
    int degN = g_deg[node];
    int n = degN < BUCKET ? degN : BUCKET;
    float di = rsqrtf((float)(degN + 1));
    const uint2* hv = (const uint2*)g_h1h;   // 4 halves per uint2; 32/row
    float4 a = h4_to_f4(hv[node * 32 + lane]);
    float w0 = di * di;
    float4 acc0 = make_float4(w0 * a.x, w0 * a.y, w0 * a.z, w0 * a.w);
    float4 acc1 = make_float4(0.f, 0.f, 0.f, 0.f);
    const int* row = &g_esrc[node * BUCKET];

    for (int base = 0; base < n; base += 32) {
        int m = n - base; if (m > 32) m = 32;
        // lane-parallel preload: lane j owns edge base+j
        int sj = (lane < m) ? row[base + lane] : 0;
        float wj = (lane < m) ? di * rsqrtf((float)(g_deg[sj] + 1)) : 0.f;
        int j = 0;
        for (; j + 4 <= m; j += 4) {
            int s0 = __shfl_sync(0xffffffffu, sj, j + 0);
            int s1 = __shfl_sync(0xffffffffu, sj, j + 1);
            int s2 = __shfl_sync(0xffffffffu, sj, j + 2);
            int s3 = __shfl_sync(0xffffffffu, sj, j + 3);
            float w0_ = __shfl_sync(0xffffffffu, wj, j + 0);
            float w1_ = __shfl_sync(0xffffffffu, wj, j + 1);
            float w2_ = __shfl_sync(0xffffffffu, wj, j + 2);
            float w3_ = __shfl_sync(0xffffffffu, wj, j + 3);
            float4 v0 = h4_to_f4(hv[s0 * 32 + lane]);
            float4 v1 = h4_to_f4(hv[s1 * 32 + lane]);
            float4 v2 = h4_to_f4(hv[s2 * 32 + lane]);
            float4 v3 = h4_to_f4(hv[s3 * 32 + lane]);
            acc0.x = fmaf(w0_, v0.x, acc0.x); acc0.y = fmaf(w0_, v0.y, acc0.y);
            acc0.z = fmaf(w0_, v0.z, acc0.z); acc0.w = fmaf(w0_, v0.w, acc0.w);
            acc1.x = fmaf(w1_, v1.x, acc1.x); acc1.y = fmaf(w1_, v1.y, acc1.y);
            acc1.z = fmaf(w1_, v1.z, acc1.z); acc1.w = fmaf(w1_, v1.w, acc1.w);
            acc0.x = fmaf(w2_, v2.x, acc0.x); acc0.y = fmaf(w2_, v2.y, acc0.y);
            acc0.z = fmaf(w2_, v2.z, acc0.z); acc0.w = fmaf(w2_, v2.w, acc0.w);
            acc1.x = fmaf(w3_, v3.x, acc1.x); acc1.y = fmaf(w3_, v3.y, acc1.y);
            acc1.z = fmaf(w3_, v3.z, acc1.z); acc1.w = fmaf(w3_, v3.w, acc1.w);
        }
        for (; j < m; j++) {
            int s = __shfl_sync(0xffffffffu, sj, j);
            float w = __shfl_sync(0xffffffffu, wj, j);
            float4 v = h4_to_f4(hv[s * 32 + lane]);
            acc0.x = fmaf(w, v.x, acc0.x); acc0.y = fmaf(w, v.y, acc0.y);
            acc0.z = fmaf(w, v.z, acc0.z); acc0.w = fmaf(w, v.w, acc0.w);
        }
    }
    float bx = bias[lane * 4 + 0], by = bias[lane * 4 + 1];
    float bz = bias[lane * 4 + 2], bw = bias[lane * 4 + 3];
    float4 r;
    r.x = fmaxf(acc0.x + acc1.x + bx, 0.f);
    r.y = fmaxf(acc0.y + acc1.y + by, 0.f);
    r.z = fmaxf(acc0.z + acc1.z + bz, 0.f);
    r.w = fmaxf(acc0.w + acc1.w + bw, 0.f);
    ((float4*)g_a1)[node * 32 + lane] = r;
}

// F=64: 2 halves per lane, + bias, NO relu (final layer), writes fp32 d_out
__global__ void agg_bias_64_kernel(const float* __restrict__ bias,
                                   float* __restrict__ out) {
    int gw = (blockIdx.x * blockDim.x + threadIdx.x) >> 5;
    int lane = threadIdx.x & 31;
    if (gw >= N_NODES) return;
    int node = gw;
    int degN = g_deg[node];
    int n = degN < BUCKET ? degN : BUCKET;
    float di = rsqrtf((float)(degN + 1));
    const uint32_t* hv = (const uint32_t*)g_h2h;  // 2 halves per u32; 32/row
    uint32_t selfraw = hv[node * 32 + lane];
    float2 a = __half22float2(*reinterpret_cast<__half2*>(&selfraw));
    float w0 = di * di;
    float2 acc0 = make_float2(w0 * a.x, w0 * a.y);
    float2 acc1 = make_float2(0.f, 0.f);
    const int* row = &g_esrc[node * BUCKET];

    for (int base = 0; base < n; base += 32) {
        int m = n - base; if (m > 32) m = 32;
        int sj = (lane < m) ? row[base + lane] : 0;
        float wj = (lane < m) ? di * rsqrtf((float)(g_deg[sj] + 1)) : 0.f;
        int j = 0;
        for (; j + 4 <= m; j += 4) {
            int s0 = __shfl_sync(0xffffffffu, sj, j + 0);
            int s1 = __shfl_sync(0xffffffffu, sj, j + 1);
            int s2 = __shfl_sync(0xffffffffu, sj, j + 2);
            int s3 = __shfl_sync(0xffffffffu, sj, j + 3);
            float w0_ = __shfl_sync(0xffffffffu, wj, j + 0);
            float w1_ = __shfl_sync(0xffffffffu, wj, j + 1);
            float w2_ = __shfl_sync(0xffffffffu, wj, j + 2);
            float w3_ = __shfl_sync(0xffffffffu, wj, j + 3);
            uint32_t r0 = hv[s0 * 32 + lane], r1 = hv[s1 * 32 + lane];
            uint32_t r2 = hv[s2 * 32 + lane], r3 = hv[s3 * 32 + lane];
            float2 v0 = __half22float2(*reinterpret_cast<__half2*>(&r0));
            float2 v1 = __half22float2(*reinterpret_cast<__half2*>(&r1));
            float2 v2 = __half22float2(*reinterpret_cast<__half2*>(&r2));
            float2 v3 = __half22float2(*reinterpret_cast<__half2*>(&r3));
            acc0.x = fmaf(w0_, v0.x, acc0.x); acc0.y = fmaf(w0_, v0.y, acc0.y);
            acc1.x = fmaf(w1_, v1.x, acc1.x); acc1.y = fmaf(w1_, v1.y, acc1.y);
            acc0.x = fmaf(w2_, v2.x, acc0.x); acc0.y = fmaf(w2_, v2.y, acc0.y);
            acc1.x = fmaf(w3_, v3.x, acc1.x); acc1.y = fmaf(w3_, v3.y, acc1.y);
        }
        for (; j < m; j++) {
            int s = __shfl_sync(0xffffffffu, sj, j);
            float w = __shfl_sync(0xffffffffu, wj, j);
            uint32_t raw = hv[s * 32 + lane];
            float2 v = __half22float2(*reinterpret_cast<__half2*>(&raw));
            acc0.x = fmaf(w, v.x, acc0.x); acc0.y = fmaf(w, v.y, acc0.y);
        }
    }
    float ox = acc0.x + acc1.x + bias[lane * 2 + 0];
    float oy = acc0.y + acc1.y + bias[lane * 2 + 1];
    out[node * 64 + lane * 2 + 0] = ox;
    out[node * 64 + lane * 2 + 1] = oy;
}

// ---------------- launch ----------------------------------------------------
extern "C" void kernel_launch(void* const* d_in, const int* in_sizes, int n_in,
                              void* d_out, int out_size) {
    const float* x  = (const float*)d_in[0];
    const void*  ei = d_in[1];                 // int32 or int64 — sniffed on device
    const float* W1 = (const float*)d_in[2];
    const float* b1 = (const float*)d_in[3];
    const float* W2 = (const float*)d_in[4];
    const float* b2 = (const float*)d_in[5];
    float* out = (float*)d_out;

    // 1. zero degree cursors + dtype sniff
    zero_detect_kernel<<<(N_NODES + 255) / 256, 256>>>(ei);
    // 2. bucket-append edges (full occupancy, standalone)
    fill_kernel<<<(N_EDGES + 255) / 256, 256>>>(ei);
    // 3. h1 = x@W1 (fp16 out)
    gemm1_kernel<<<GEMM_BLOCKS, 256>>>(x, W1);
    // 4. a1 = relu(agg(h1) + b1)
    agg_relu_bias_128_kernel<<<(N_NODES * 32 + 255) / 256, 256>>>(b1);
    // 5. h2 = a1@W2 (fp16 out)
    gemm2_kernel<<<GEMM_BLOCKS, 256>>>(W2);
    // 6. out = agg(h2) + b2
    agg_bias_64_kernel<<<(N_NODES * 32 + 255) / 256, 256>>>(b2, out);
}

// round 15
// speedup vs baseline: 1.1057x; 1.0114x over previous
#include <cuda_runtime.h>
#include <cuda_fp16.h>
#include <cstdint>

#define N_NODES 50000
#define N_EDGES 600000
#define F_MID 128
#define F_OUT 64
#define BUCKET 64                         // max in-degree slots per node
#define GEMM_BLOCKS ((N_NODES + 127) / 128)           // 391

// ---------------- scratch (static __device__, 256B-aligned) ----------------
__device__ __align__(256) __half g_h1h[N_NODES * F_MID]; // x @ W1   (fp16)
__device__ __align__(256) float  g_a1[N_NODES * F_MID];  // relu(agg1 + b1)
__device__ __align__(256) __half g_h2h[N_NODES * F_OUT]; // a1 @ W2  (fp16)
__device__ __align__(256) int    g_deg[N_NODES];         // atomic cursor == in-degree
__device__ __align__(256) int    g_esrc[N_NODES * BUCKET];
__device__ int g_is64;   // 1 if edge_index is int64, 0 if int32

__device__ __forceinline__ int load_edge(const void* ei, long long idx) {
    if (g_is64) return (int)((const long long*)ei)[idx];
    return ((const int*)ei)[idx];
}

// ---------------- zero degrees + dtype sniff --------------------------------
// int64 vals < 50000 look like [v,0,v,0,...] as int32 pairs
__global__ void zero_detect_kernel(const void* __restrict__ ei) {
    int i = blockIdx.x * blockDim.x + threadIdx.x;
    if (i < N_NODES) g_deg[i] = 0;
    if (i == 0) {
        const int* p = (const int*)ei;
        int allz = 1;
        for (int k = 0; k < 128; k++)
            if (p[2 * k + 1] != 0) { allz = 0; break; }
        g_is64 = allz;
    }
}

// ---------------- bucket fill: 4 edges/thread, vectorized -------------------
__global__ void fill_kernel(const void* __restrict__ ei) {
    int t = blockIdx.x * blockDim.x + threadIdx.x;
    int e0 = t * 4;
    if (e0 >= N_EDGES) return;
    int s4[4], d4[4];
    if (!g_is64) {
        const int* p = (const int*)ei;
        *(int4*)s4 = *(const int4*)&p[e0];
        *(int4*)d4 = *(const int4*)&p[N_EDGES + e0];
    } else {
        const long long* p = (const long long*)ei;
        #pragma unroll
        for (int k = 0; k < 4; k++) {
            s4[k] = (int)p[e0 + k];
            d4[k] = (int)p[(long long)N_EDGES + e0 + k];
        }
    }
    #pragma unroll
    for (int k = 0; k < 4; k++) {
        int e = e0 + k;
        if (e < N_EDGES) {
            int s = s4[k], d = d4[k];
            if ((unsigned)d < (unsigned)N_NODES && (unsigned)s < (unsigned)N_NODES) {
                int idx = atomicAdd(&g_deg[d], 1);
                if (idx < BUCKET) g_esrc[d * BUCKET + idx] = s;
            }
        }
    }
}

// ---------------- fp16 tensor-core GEMM tile (device fn) --------------------
// Chalf[128 rows][BN] = A[M,128] * B[128,BN]; 256 thr = 8 warps (2x4).
// A,B fp32 in gmem; converted to fp16 at smem-commit; mma m16n8k16 fp32-acc.
template <int BN>
__device__ __forceinline__ void gemm_tile(const float* __restrict__ A,
                                          const float* __restrict__ B,
                                          __half* __restrict__ C, int block) {
    constexpr int BM = 128, BK = 32;
    constexpr int MT = 4;                 // 64 rows / 16
    constexpr int NT = (BN / 4) / 8;      // 4 (BN=128) or 2 (BN=64)
    constexpr int NAv = 4;                // A float4 loads/thread
    constexpr int NBv = BN / 32;          // B float4 loads/thread
    constexpr int AP = BK + 8;            // 40 halves/row (80B) conflict-free
    constexpr int BP = BN + 8;
    const int M = N_NODES;

    __shared__ __half As[BM][AP];
    __shared__ __half Bs[BK][BP];

    int tid = threadIdx.x;
    int lane = tid & 31;
    int w = tid >> 5;
    int warp_m = w >> 2, warp_n = w & 3;
    int mrow0 = warp_m * 64;
    int ncol0 = warp_n * (BN / 4);
    int g = lane >> 2, q = lane & 3;
    int row0 = block * BM;

    float acc[MT][NT][4];
    #pragma unroll
    for (int i = 0; i < MT; i++)
        #pragma unroll
        for (int j = 0; j < NT; j++)
            #pragma unroll
            for (int k = 0; k < 4; k++) acc[i][j][k] = 0.f;

    float4 ra[NAv], rb[NBv];
    auto fetch = [&](int kb) {
        #pragma unroll
        for (int k = 0; k < NAv; k++) {
            int idx = tid + k * 256;
            int ar = idx >> 3, ac4 = idx & 7;
            int gr = row0 + ar;
            ra[k] = (gr < M) ? *(const float4*)&A[gr * 128 + kb + ac4 * 4]
                             : make_float4(0.f, 0.f, 0.f, 0.f);
        }
        #pragma unroll
        for (int k = 0; k < NBv; k++) {
            int idx = tid + k * 256;
            int br = idx / (BN / 4), bc4 = idx % (BN / 4);
            rb[k] = *(const float4*)&B[(kb + br) * BN + bc4 * 4];
        }
    };
    auto commit = [&]() {
        #pragma unroll
        for (int k = 0; k < NAv; k++) {
            int idx = tid + k * 256;
            int ar = idx >> 3, ac4 = idx & 7;
            __half2 h01 = __floats2half2_rn(ra[k].x, ra[k].y);
            __half2 h23 = __floats2half2_rn(ra[k].z, ra[k].w);
            uint2 v = make_uint2(*(uint32_t*)&h01, *(uint32_t*)&h23);
            *(uint2*)&As[ar][ac4 * 4] = v;            // 80B rows: 8B-aligned
        }
        #pragma unroll
        for (int k = 0; k < NBv; k++) {
            int idx = tid + k * 256;
            int br = idx / (BN / 4), bc4 = idx % (BN / 4);
            __half2 h01 = __floats2half2_rn(rb[k].x, rb[k].y);
            __half2 h23 = __floats2half2_rn(rb[k].z, rb[k].w);
            uint2 v = make_uint2(*(uint32_t*)&h01, *(uint32_t*)&h23);
            *(uint2*)&Bs[br][bc4 * 4] = v;
        }
    };

    fetch(0);
    #pragma unroll
    for (int t = 0; t < 128 / BK; t++) {
        commit();
        __syncthreads();
        if (t < 128 / BK - 1) fetch((t + 1) * BK);
        #pragma unroll
        for (int ks = 0; ks < BK / 16; ks++) {        // 2 k16-steps per tile
            int k0 = ks * 16;
            uint32_t af[MT][4];
            #pragma unroll
            for (int mt = 0; mt < MT; mt++) {
                int r = mrow0 + mt * 16 + g;
                af[mt][0] = *(uint32_t*)&As[r][k0 + 2 * q];
                af[mt][1] = *(uint32_t*)&As[r + 8][k0 + 2 * q];
                af[mt][2] = *(uint32_t*)&As[r][k0 + 2 * q + 8];
                af[mt][3] = *(uint32_t*)&As[r + 8][k0 + 2 * q + 8];
            }
            uint32_t bf[NT][2];
            #pragma unroll
            for (int nt = 0; nt < NT; nt++) {
                int c = ncol0 + nt * 8 + g;
                __half2 b0 = __halves2half2(Bs[k0 + 2 * q][c], Bs[k0 + 2 * q + 1][c]);
                __half2 b1 = __halves2half2(Bs[k0 + 2 * q + 8][c], Bs[k0 + 2 * q + 9][c]);
                bf[nt][0] = *(uint32_t*)&b0;
                bf[nt][1] = *(uint32_t*)&b1;
            }
            #pragma unroll
            for (int mt = 0; mt < MT; mt++)
                #pragma unroll
                for (int nt = 0; nt < NT; nt++) {
                    asm volatile(
                        "mma.sync.aligned.m16n8k16.row.col.f32.f16.f16.f32 "
                        "{%0,%1,%2,%3}, {%4,%5,%6,%7}, {%8,%9}, {%0,%1,%2,%3};"
                        : "+f"(acc[mt][nt][0]), "+f"(acc[mt][nt][1]),
                          "+f"(acc[mt][nt][2]), "+f"(acc[mt][nt][3])
                        : "r"(af[mt][0]), "r"(af[mt][1]),
                          "r"(af[mt][2]), "r"(af[mt][3]),
                          "r"(bf[nt][0]), "r"(bf[nt][1]));
                }
        }
        __syncthreads();
    }

    #pragma unroll
    for (int mt = 0; mt < MT; mt++) {
        int r = mrow0 + mt * 16 + g;
        int gr0 = row0 + r, gr1 = gr0 + 8;
        #pragma unroll
        for (int nt = 0; nt < NT; nt++) {
            int c = ncol0 + nt * 8 + 2 * q;
            if (gr0 < M)
                *(__half2*)&C[gr0 * BN + c] =
                    __floats2half2_rn(acc[mt][nt][0], acc[mt][nt][1]);
            if (gr1 < M)
                *(__half2*)&C[gr1 * BN + c] =
                    __floats2half2_rn(acc[mt][nt][2], acc[mt][nt][3]);
        }
    }
}

__global__ void gemm1_kernel(const float* __restrict__ x,
                             const float* __restrict__ W1) {
    gemm_tile<128>(x, W1, g_h1h, blockIdx.x);
}

__global__ void gemm2_kernel(const float* __restrict__ W2) {
    gemm_tile<64>((const float*)g_a1, W2, g_h2h, blockIdx.x);
}

// ---------------- aggregation: warp-per-node, lane-preload, MLP=8 ----------
__device__ __forceinline__ float4 h4_to_f4(uint2 r) {
    __half2 a = *reinterpret_cast<__half2*>(&r.x);
    __half2 b = *reinterpret_cast<__half2*>(&r.y);
    float2 fa = __half22float2(a), fb = __half22float2(b);
    return make_float4(fa.x, fa.y, fb.x, fb.y);
}

// g_a1[i] = relu( dinv_i^2*h1[i] + sum_e dinv_s*dinv_i*h1[s] + b1 ), F=128
__global__ void agg_relu_bias_128_kernel(const float* __restrict__ bias) {
    int gw = (blockIdx.x * blockDim.x + threadIdx.x) >> 5;
    int lane = threadIdx.x & 31;
    if (gw >= N_NODES) return;
    int node = gw;
    int degN = g_deg[node];
    int n = degN < BUCKET ? degN : BUCKET;
    float di = rsqrtf((float)(degN + 1));
    const uint2* hv = (const uint2*)g_h1h;   // 4 halves per uint2; 32/row
    float4 a = h4_to_f4(hv[node * 32 + lane]);
    float w0 = di * di;
    float4 acc0 = make_float4(w0 * a.x, w0 * a.y, w0 * a.z, w0 * a.w);
    float4 acc1 = make_float4(0.f, 0.f, 0.f, 0.f);
    const int* row = &g_esrc[node * BUCKET];

    for (int base = 0; base < n; base += 32) {
        int m = n - base; if (m > 32) m = 32;
        // lane-parallel preload: lane j owns edge base+j
        int sj = (lane < m) ? row[base + lane] : 0;
        float wj = (lane < m) ? di * rsqrtf((float)(g_deg[sj] + 1)) : 0.f;
        int j = 0;
        for (; j + 8 <= m; j += 8) {                 // MLP = 8
            int s[8]; float ww[8]; uint2 raw[8];
            #pragma unroll
            for (int k = 0; k < 8; k++) {
                s[k]  = __shfl_sync(0xffffffffu, sj, j + k);
                ww[k] = __shfl_sync(0xffffffffu, wj, j + k);
            }
            #pragma unroll
            for (int k = 0; k < 8; k++) raw[k] = hv[s[k] * 32 + lane];
            #pragma unroll
            for (int k = 0; k < 8; k++) {
                float4 v = h4_to_f4(raw[k]);
                float4& ac = (k & 1) ? acc1 : acc0;
                ac.x = fmaf(ww[k], v.x, ac.x); ac.y = fmaf(ww[k], v.y, ac.y);
                ac.z = fmaf(ww[k], v.z, ac.z); ac.w = fmaf(ww[k], v.w, ac.w);
            }
        }
        for (; j + 4 <= m; j += 4) {
            int s[4]; float ww[4]; uint2 raw[4];
            #pragma unroll
            for (int k = 0; k < 4; k++) {
                s[k]  = __shfl_sync(0xffffffffu, sj, j + k);
                ww[k] = __shfl_sync(0xffffffffu, wj, j + k);
            }
            #pragma unroll
            for (int k = 0; k < 4; k++) raw[k] = hv[s[k] * 32 + lane];
            #pragma unroll
            for (int k = 0; k < 4; k++) {
                float4 v = h4_to_f4(raw[k]);
                float4& ac = (k & 1) ? acc1 : acc0;
                ac.x = fmaf(ww[k], v.x, ac.x); ac.y = fmaf(ww[k], v.y, ac.y);
                ac.z = fmaf(ww[k], v.z, ac.z); ac.w = fmaf(ww[k], v.w, ac.w);
            }
        }
        for (; j < m; j++) {
            int s = __shfl_sync(0xffffffffu, sj, j);
            float w = __shfl_sync(0xffffffffu, wj, j);
            float4 v = h4_to_f4(hv[s * 32 + lane]);
            acc0.x = fmaf(w, v.x, acc0.x); acc0.y = fmaf(w, v.y, acc0.y);
            acc0.z = fmaf(w, v.z, acc0.z); acc0.w = fmaf(w, v.w, acc0.w);
        }
    }
    float bx = bias[lane * 4 + 0], by = bias[lane * 4 + 1];
    float bz = bias[lane * 4 + 2], bw = bias[lane * 4 + 3];
    float4 r;
    r.x = fmaxf(acc0.x + acc1.x + bx, 0.f);
    r.y = fmaxf(acc0.y + acc1.y + by, 0.f);
    r.z = fmaxf(acc0.z + acc1.z + bz, 0.f);
    r.w = fmaxf(acc0.w + acc1.w + bw, 0.f);
    ((float4*)g_a1)[node * 32 + lane] = r;
}

// F=64: 2 halves per lane, + bias, NO relu (final layer), writes fp32 d_out
__global__ void agg_bias_64_kernel(const float* __restrict__ bias,
                                   float* __restrict__ out) {
    int gw = (blockIdx.x * blockDim.x + threadIdx.x) >> 5;
    int lane = threadIdx.x & 31;
    if (gw >= N_NODES) return;
    int node = gw;
    int degN = g_deg[node];
    int n = degN < BUCKET ? degN : BUCKET;
    float di = rsqrtf((float)(degN + 1));
    const uint32_t* hv = (const uint32_t*)g_h2h;  // 2 halves per u32; 32/row
    uint32_t selfraw = hv[node * 32 + lane];
    float2 a = __half22float2(*reinterpret_cast<__half2*>(&selfraw));
    float w0 = di * di;
    float2 acc0 = make_float2(w0 * a.x, w0 * a.y);
    float2 acc1 = make_float2(0.f, 0.f);
    const int* row = &g_esrc[node * BUCKET];

    for (int base = 0; base < n; base += 32) {
        int m = n - base; if (m > 32) m = 32;
        int sj = (lane < m) ? row[base + lane] : 0;
        float wj = (lane < m) ? di * rsqrtf((float)(g_deg[sj] + 1)) : 0.f;
        int j = 0;
        for (; j + 8 <= m; j += 8) {
            int s[8]; float ww[8]; uint32_t raw[8];
            #pragma unroll
            for (int k = 0; k < 8; k++) {
                s[k]  = __shfl_sync(0xffffffffu, sj, j + k);
                ww[k] = __shfl_sync(0xffffffffu, wj, j + k);
            }
            #pragma unroll
            for (int k = 0; k < 8; k++) raw[k] = hv[s[k] * 32 + lane];
            #pragma unroll
            for (int k = 0; k < 8; k++) {
                float2 v = __half22float2(*reinterpret_cast<__half2*>(&raw[k]));
                float2& ac = (k & 1) ? acc1 : acc0;
                ac.x = fmaf(ww[k], v.x, ac.x); ac.y = fmaf(ww[k], v.y, ac.y);
            }
        }
        for (; j + 4 <= m; j += 4) {
            int s[4]; float ww[4]; uint32_t raw[4];
            #pragma unroll
            for (int k = 0; k < 4; k++) {
                s[k]  = __shfl_sync(0xffffffffu, sj, j + k);
                ww[k] = __shfl_sync(0xffffffffu, wj, j + k);
            }
            #pragma unroll
            for (int k = 0; k < 4; k++) raw[k] = hv[s[k] * 32 + lane];
            #pragma unroll
            for (int k = 0; k < 4; k++) {
                float2 v = __half22float2(*reinterpret_cast<__half2*>(&raw[k]));
                float2& ac = (k & 1) ? acc1 : acc0;
                ac.x = fmaf(ww[k], v.x, ac.x); ac.y = fmaf(ww[k], v.y, ac.y);
            }
        }
        for (; j < m; j++) {
            int s = __shfl_sync(0xffffffffu, sj, j);
            float w = __shfl_sync(0xffffffffu, wj, j);
            uint32_t raw = hv[s * 32 + lane];
            float2 v = __half22float2(*reinterpret_cast<__half2*>(&raw));
            acc0.x = fmaf(w, v.x, acc0.x); acc0.y = fmaf(w, v.y, acc0.y);
        }
    }
    float ox = acc0.x + acc1.x + bias[lane * 2 + 0];
    float oy = acc0.y + acc1.y + bias[lane * 2 + 1];
    out[node * 64 + lane * 2 + 0] = ox;
    out[node * 64 + lane * 2 + 1] = oy;
}

// ---------------- launch ----------------------------------------------------
extern "C" void kernel_launch(void* const* d_in, const int* in_sizes, int n_in,
                              void* d_out, int out_size) {
    const float* x  = (const float*)d_in[0];
    const void*  ei = d_in[1];                 // int32 or int64 — sniffed on device
    const float* W1 = (const float*)d_in[2];
    const float* b1 = (const float*)d_in[3];
    const float* W2 = (const float*)d_in[4];
    const float* b2 = (const float*)d_in[5];
    float* out = (float*)d_out;

    // 1. zero degree cursors + dtype sniff
    zero_detect_kernel<<<(N_NODES + 255) / 256, 256>>>(ei);
    // 2. bucket-append edges (4 edges/thread, vectorized loads)
    fill_kernel<<<(N_EDGES / 4 + 255) / 256, 256>>>(ei);
    // 3. h1 = x@W1 (fp16 mma, fp16 out)
    gemm1_kernel<<<GEMM_BLOCKS, 256>>>(x, W1);
    // 4. a1 = relu(agg(h1) + b1)
    agg_relu_bias_128_kernel<<<(N_NODES * 32 + 255) / 256, 256>>>(b1);
    // 5. h2 = a1@W2 (fp16 mma, fp16 out)
    gemm2_kernel<<<GEMM_BLOCKS, 256>>>(W2);
    // 6. out = agg(h2) + b2
    agg_bias_64_kernel<<<(N_NODES * 32 + 255) / 256, 256>>>(b2, out);
}